// round 15
// baseline (speedup 1.0000x reference)
#include <cuda_runtime.h>
#include <math.h>

#define N_RES  20000
#define N_EDGE 640000
#define FDIM   340
#define REC    48

// ---------------- device scratch (no allocations allowed) ----------------
__device__ float g_freq[8];             // positional frequencies (match XLA f32 exp)
// packed per-residue record (48 floats = 192B):
// [0:12) bb (N,CA,C,CB) | [12:24) local=R^T(bb-t) premul by keep | [24:33) R[j*3+i] | [33:36) t
// [36] noised [37] keep [38] seq_f [39] pad
__device__ float g_node[N_RES * REC];

// ---------------- per-residue precompute (mask dtype detected per block) ----------------
__global__ void node_kernel(const float* __restrict__ atom14,
                            const float* __restrict__ rig,
                            const int*   __restrict__ seq,
                            const void*  __restrict__ maskp) {
    // PDL: allow the dependent edge_kernel to begin launching immediately;
    // its cudaGridDependencySynchronize() still waits for our completion+flush.
    cudaTriggerProgrammaticLaunchCompletion();

    __shared__ int s_mode;
    int r = blockIdx.x * blockDim.x + threadIdx.x;

    // mask dtype detection: ONE thread per block scans 64 words, broadcasts via smem
    if (threadIdx.x == 0) {
        const unsigned* mw = (const unsigned*)maskp;
        bool isF = false, isB = false;
        #pragma unroll
        for (int i = 0; i < 64; ++i) {
            unsigned v = __ldg(mw + i);
            isF |= (v == 0x3F800000u);
            isB |= (v != 0u && v != 1u);
        }
        s_mode = isB ? 2 : (isF ? 0 : 1);
    }
    __syncthreads();
    if (r >= N_RES) return;
    int mode = s_mode;

    // positional freqs (threads 0..7): exact f32 rounding like XLA
    if (r < 8) {
        const float basef = -0.5756462732485115f;   // float(-ln(10000)/16)
        float arg = (float)(2 * r) * basef;
        g_freq[r] = (float)exp((double)arg);
    }

    unsigned char mv;
    if (mode == 2)      mv = (((const unsigned char*)maskp)[r] != 0);
    else if (mode == 1) mv = (((const int*)maskp)[r] != 0);
    else                mv = (((const float*)maskp)[r] != 0.0f);
    float noised = mv ? 1.0f : 0.0f;
    float keep   = 1.0f - noised;

    const float* a = atom14 + (size_t)r * 14 * 3;
    float n0 = a[0], n1 = a[1], n2 = a[2];
    float ca0 = a[3], ca1 = a[4], ca2 = a[5];
    float c0 = a[6], c1 = a[7], c2 = a[8];

    float bx = ca0 - n0, by = ca1 - n1, bz = ca2 - n2;
    float cx = c0 - ca0, cy = c1 - ca1, cz = c2 - ca2;
    float ax = by * cz - bz * cy;
    float ay = bz * cx - bx * cz;
    float az = bx * cy - by * cx;
    float cb0 = -0.58273431f * ax + 0.56802827f * bx - 0.54067466f * cx + ca0;
    float cb1 = -0.58273431f * ay + 0.56802827f * by - 0.54067466f * cy + ca1;
    float cb2 = -0.58273431f * az + 0.56802827f * bz - 0.54067466f * cz + ca2;

    float bb[4][3] = {{n0, n1, n2}, {ca0, ca1, ca2}, {c0, c1, c2}, {cb0, cb1, cb2}};

    const float* q = rig + (size_t)r * 7;
    float w = q[0], x = q[1], y = q[2], z = q[3];
    float inv = rsqrtf(w * w + x * x + y * y + z * z);
    w *= inv; x *= inv; y *= inv; z *= inv;

    float R[3][3];
    R[0][0] = 1.0f - 2.0f * (y * y + z * z);
    R[0][1] = 2.0f * (x * y - w * z);
    R[0][2] = 2.0f * (x * z + w * y);
    R[1][0] = 2.0f * (x * y + w * z);
    R[1][1] = 1.0f - 2.0f * (x * x + z * z);
    R[1][2] = 2.0f * (y * z - w * x);
    R[2][0] = 2.0f * (x * z - w * y);
    R[2][1] = 2.0f * (y * z + w * x);
    R[2][2] = 1.0f - 2.0f * (x * x + y * y);

    float t0 = q[4], t1 = q[5], t2 = q[6];

    float* N_ = g_node + r * REC;
    #pragma unroll
    for (int k = 0; k < 4; ++k) {
        N_[k * 3 + 0] = bb[k][0];
        N_[k * 3 + 1] = bb[k][1];
        N_[k * 3 + 2] = bb[k][2];
        float d0 = bb[k][0] - t0, d1 = bb[k][1] - t1, d2 = bb[k][2] - t2;
        #pragma unroll
        for (int i = 0; i < 3; ++i) {
            N_[12 + k * 3 + i] = (R[0][i] * d0 + R[1][i] * d1 + R[2][i] * d2) * keep;
        }
    }
    #pragma unroll
    for (int j = 0; j < 3; ++j) {
        N_[24 + j * 3 + 0] = R[j][0];
        N_[24 + j * 3 + 1] = R[j][1];
        N_[24 + j * 3 + 2] = R[j][2];
    }
    N_[33] = t0; N_[34] = t1; N_[35] = t2;
    N_[36] = noised; N_[37] = keep; N_[38] = (float)seq[r]; N_[39] = 0.0f;
}

// ---------------- helpers ----------------
__device__ __forceinline__ float ex2(float x) {
    float y;
    asm("ex2.approx.f32 %0, %1;" : "=f"(y) : "f"(x));
    return y;
}

__device__ __forceinline__ float reduce_2pi(float ang) {
    const float INV_2PI = 0.15915494309189535f;
    const float HI = 6.28125f;
    const float LO = 1.9353071795864769e-3f;
    float k = rintf(ang * INV_2PI);
    float r = fmaf(-k, HI, ang);
    r = fmaf(-k, LO, r);
    return r;
}

// ---------------- edge kernel: TWO edges per warp (half-warp per edge) ----------------
// (R11 winner + PDL prologue overlap)
__global__ void __launch_bounds__(256) edge_kernel(const int* __restrict__ ei,
                                                   float* __restrict__ out) {
    const unsigned FULL = 0xFFFFFFFFu;
    int W = (blockIdx.x * 256 + threadIdx.x) >> 5;   // warp id: edges 2W, 2W+1
    int lane = threadIdx.x & 31;
    int hl = lane & 15;        // lane within half
    int hb = lane & 16;        // half base (0 or 16)
    int half = lane >> 4;

    // ---- node-independent prologue (overlaps with node_kernel via PDL) ----
    int2 dpair = *(const int2*)(ei + 2 * W);             // dst of edges 2W, 2W+1
    int2 spair = *(const int2*)(ei + N_EDGE + 2 * W);    // src

    int dst = half ? dpair.y : dpair.x;
    int src = half ? spair.y : spair.x;

    float* rowE = out + (size_t)(2 * W + half) * FDIM;
    float* row0 = out + (size_t)(2 * W) * FDIM;
    float* row1 = row0 + FDIM;

    // RBF constants (node-independent)
    const float C = 0.9608979270291598f;
    int rbase = (lane * 4) & 15;
    float c0 = fmaf((float)(rbase + 0), 4.0f / 3.0f, 2.0f) * (-C);
    float c1 = fmaf((float)(rbase + 1), 4.0f / 3.0f, 2.0f) * (-C);
    float c2 = fmaf((float)(rbase + 2), 4.0f / 3.0f, 2.0f) * (-C);
    float c3 = fmaf((float)(rbase + 3), 4.0f / 3.0f, 2.0f) * (-C);
    int pbase = lane >> 2;

    const float* SR = g_node + src * REC;
    const float* DR = g_node + dst * REC;

    // ---- wait for node_kernel's g_node / g_freq writes to be visible ----
    cudaGridDependencySynchronize();

    // per-half cooperative loads (lanes 0..11 of each half)
    float sv = 0.0f, dv = 0.0f, lv = 0.0f, bv = 0.0f;
    if (hl < 12) {
        sv = SR[hl];          // src bb
        dv = DR[hl];          // dst bb
        lv = SR[12 + hl];     // src local * keep_s
        bv = SR[24 + hl];     // src R (9) + t (3)
    }
    // per-half scalar records (broadcast within half, 2 addresses per warp)
    float4 ssE = *(const float4*)(SR + 36);   // noised_s, keep_s, seqf_s
    float4 dsE = *(const float4*)(DR + 36);   // noised_d, keep_d, seqf_d

    // ---- segment A: cols 0..43, single pass, both edges at once ----
    {
        float lf = (float)hl;
        // col hl: 0=noised_d, 1=noised_s, 2..15 = src one-hot idx hl-2
        float v0;
        if (hl == 0)      v0 = dsE.x;
        else if (hl == 1) v0 = ssE.x;
        else              v0 = (ssE.z == lf - 2.0f) ? ssE.y : 0.0f;
        __stcs(rowE + hl, v0);
        // col 16+hl: hl<7 -> src idx hl+14; else dst idx hl-7
        float v1 = (hl < 7) ? ((ssE.z == lf + 14.0f) ? ssE.y : 0.0f)
                            : ((dsE.z == lf - 7.0f)  ? dsE.y : 0.0f);
        __stcs(rowE + 16 + hl, v1);
        // col 32+hl (hl<12): dst idx hl+9
        if (hl < 12) __stcs(rowE + 32 + hl, (dsE.z == lf + 9.0f) ? dsE.y : 0.0f);
    }

    // ---- distances: every lane owns one pair of its half's edge ----
    float dve = 1e-8f - dv;
    int i3 = ((lane >> 2) & 3) * 3;
    int j3 = (lane & 3) * 3;
    float dx = __shfl_sync(FULL, sv, hb + i3 + 0) + __shfl_sync(FULL, dve, hb + j3 + 0);
    float dy = __shfl_sync(FULL, sv, hb + i3 + 1) + __shfl_sync(FULL, dve, hb + j3 + 1);
    float dz = __shfl_sync(FULL, sv, hb + i3 + 2) + __shfl_sync(FULL, dve, hb + j3 + 2);
    float dist = sqrtf(fmaf(dx, dx, fmaf(dy, dy, dz * dz)));
    // dist for edge e lives in lanes [e*16, e*16+16), pair p at lane e*16+p

    // ---- segment B: RBF, cols 44..299 as float4 slots (STG.128), per edge ----
    // exp(-((D-mu)/1.25)^2) == 2^(-((D-mu)*C)^2), C = 0.8*sqrt(log2 e)
    #pragma unroll
    for (int e = 0; e < 2; ++e) {
        float4* rb4 = (float4*)((e ? row1 : row0) + 44);
        #pragma unroll
        for (int it = 0; it < 2; ++it) {
            float D = __shfl_sync(FULL, dist, e * 16 + pbase + it * 8);
            float z0 = fmaf(D, C, c0);
            float z1 = fmaf(D, C, c1);
            float z2 = fmaf(D, C, c2);
            float z3 = fmaf(D, C, c3);
            float4 v;
            v.x = ex2(-z0 * z0);
            v.y = ex2(-z1 * z1);
            v.z = ex2(-z2 * z2);
            v.w = ex2(-z3 * z3);
            __stcs(rb4 + it * 32 + lane, v);
        }
    }

    // ---- segment C: positional encoding, cols 300..315, per half ----
    {
        float dpos = (float)(dst - src);
        float ang = dpos * g_freq[hl & 7];
        float r = reduce_2pi(ang);
        float v = (hl < 8) ? __cosf(r) : __sinf(r);
        __stcs(rowE + 300 + hl, v);
    }

    // ---- segment D: cols 316..327 src_bb_local (premul), 328..339 dst_in_src ----
    {
        int k3 = (hl / 3) * 3, i_ = hl - k3;    // valid for hl<12; hl>=12 unused
        float r0 = __shfl_sync(FULL, bv, hb + 0 + i_);
        float r1 = __shfl_sync(FULL, bv, hb + 3 + i_);
        float r2 = __shfl_sync(FULL, bv, hb + 6 + i_);
        float t0 = __shfl_sync(FULL, bv, hb + 9);
        float t1 = __shfl_sync(FULL, bv, hb + 10);
        float t2 = __shfl_sync(FULL, bv, hb + 11);
        float b0 = __shfl_sync(FULL, dv, hb + k3 + 0);
        float b1 = __shfl_sync(FULL, dv, hb + k3 + 1);
        float b2 = __shfl_sync(FULL, dv, hb + k3 + 2);
        float dis = fmaf(r0, b0 - t0, fmaf(r1, b1 - t1, r2 * (b2 - t2)));
        if (hl < 12) {
            __stcs(rowE + 316 + hl, lv);             // already premultiplied by keep_s
            __stcs(rowE + 328 + hl, dis * dsE.y);    // * keep_d
        }
    }
}

// ---------------- launch ----------------
extern "C" void kernel_launch(void* const* d_in, const int* in_sizes, int n_in,
                              void* d_out, int out_size) {
    const float* atom14 = (const float*)d_in[0];
    const float* rig    = (const float*)d_in[1];
    const int*   seq    = (const int*)d_in[2];
    const void*  mask   = d_in[3];
    const int*   ei     = (const int*)d_in[4];
    float*       out    = (float*)d_out;

    node_kernel<<<(N_RES + 127) / 128, 128>>>(atom14, rig, seq, mask);

    // edge_kernel with programmatic dependent launch: prologue overlaps node_kernel
    cudaLaunchConfig_t cfg = {};
    cfg.gridDim  = dim3(N_EDGE / 16, 1, 1);
    cfg.blockDim = dim3(256, 1, 1);
    cfg.dynamicSmemBytes = 0;
    cudaLaunchAttribute attrs[1];
    attrs[0].id = cudaLaunchAttributeProgrammaticStreamSerialization;
    attrs[0].val.programmaticStreamSerializationAllowed = 1;
    cfg.attrs = attrs;
    cfg.numAttrs = 1;
    cudaLaunchKernelEx(&cfg, edge_kernel, ei, out);
}

// round 16
// speedup vs baseline: 1.0178x; 1.0178x over previous
#include <cuda_runtime.h>
#include <math.h>

#define N_RES  20000
#define N_EDGE 640000
#define FDIM   340
#define REC    48

// ---------------- device scratch (no allocations allowed) ----------------
__device__ float g_freq[8];             // positional frequencies (match XLA f32 exp)
// packed per-residue record (48 floats = 192B):
// [0:12) bb (N,CA,C,CB) | [12:24) local=R^T(bb-t) premul by keep | [24:33) R[j*3+i] | [33:36) t
// [36] noised [37] keep [38] seq_f [39] pad
__device__ float g_node[N_RES * REC];

// ---------------- per-residue precompute (mask dtype detected inline) ----------------
__global__ void node_kernel(const float* __restrict__ atom14,
                            const float* __restrict__ rig,
                            const int*   __restrict__ seq,
                            const void*  __restrict__ maskp) {
    int r = blockIdx.x * blockDim.x + threadIdx.x;
    if (r >= N_RES) return;

    // positional freqs (threads 0..7): exact f32 rounding like XLA
    if (r < 8) {
        const float basef = -0.5756462732485115f;   // float(-ln(10000)/16)
        float arg = (float)(2 * r) * basef;
        g_freq[r] = (float)exp((double)arg);
    }

    // mask dtype detection: scan 64 words (uniform across threads -> L1 broadcast)
    const unsigned* mw = (const unsigned*)maskp;
    bool isF = false, isB = false;
    #pragma unroll
    for (int i = 0; i < 64; ++i) {
        unsigned v = __ldg(mw + i);
        isF |= (v == 0x3F800000u);
        isB |= (v != 0u && v != 1u);
    }
    int mode = isB ? 2 : (isF ? 0 : 1);

    unsigned char mv;
    if (mode == 2)      mv = (((const unsigned char*)maskp)[r] != 0);
    else if (mode == 1) mv = (((const int*)maskp)[r] != 0);
    else                mv = (((const float*)maskp)[r] != 0.0f);
    float noised = mv ? 1.0f : 0.0f;
    float keep   = 1.0f - noised;

    const float* a = atom14 + (size_t)r * 14 * 3;
    float n0 = a[0], n1 = a[1], n2 = a[2];
    float ca0 = a[3], ca1 = a[4], ca2 = a[5];
    float c0 = a[6], c1 = a[7], c2 = a[8];

    float bx = ca0 - n0, by = ca1 - n1, bz = ca2 - n2;
    float cx = c0 - ca0, cy = c1 - ca1, cz = c2 - ca2;
    float ax = by * cz - bz * cy;
    float ay = bz * cx - bx * cz;
    float az = bx * cy - by * cx;
    float cb0 = -0.58273431f * ax + 0.56802827f * bx - 0.54067466f * cx + ca0;
    float cb1 = -0.58273431f * ay + 0.56802827f * by - 0.54067466f * cy + ca1;
    float cb2 = -0.58273431f * az + 0.56802827f * bz - 0.54067466f * cz + ca2;

    float bb[4][3] = {{n0, n1, n2}, {ca0, ca1, ca2}, {c0, c1, c2}, {cb0, cb1, cb2}};

    const float* q = rig + (size_t)r * 7;
    float w = q[0], x = q[1], y = q[2], z = q[3];
    float inv = rsqrtf(w * w + x * x + y * y + z * z);
    w *= inv; x *= inv; y *= inv; z *= inv;

    float R[3][3];
    R[0][0] = 1.0f - 2.0f * (y * y + z * z);
    R[0][1] = 2.0f * (x * y - w * z);
    R[0][2] = 2.0f * (x * z + w * y);
    R[1][0] = 2.0f * (x * y + w * z);
    R[1][1] = 1.0f - 2.0f * (x * x + z * z);
    R[1][2] = 2.0f * (y * z - w * x);
    R[2][0] = 2.0f * (x * z - w * y);
    R[2][1] = 2.0f * (y * z + w * x);
    R[2][2] = 1.0f - 2.0f * (x * x + y * y);

    float t0 = q[4], t1 = q[5], t2 = q[6];

    float* N_ = g_node + r * REC;
    #pragma unroll
    for (int k = 0; k < 4; ++k) {
        N_[k * 3 + 0] = bb[k][0];
        N_[k * 3 + 1] = bb[k][1];
        N_[k * 3 + 2] = bb[k][2];
        float d0 = bb[k][0] - t0, d1 = bb[k][1] - t1, d2 = bb[k][2] - t2;
        #pragma unroll
        for (int i = 0; i < 3; ++i) {
            N_[12 + k * 3 + i] = (R[0][i] * d0 + R[1][i] * d1 + R[2][i] * d2) * keep;
        }
    }
    #pragma unroll
    for (int j = 0; j < 3; ++j) {
        N_[24 + j * 3 + 0] = R[j][0];
        N_[24 + j * 3 + 1] = R[j][1];
        N_[24 + j * 3 + 2] = R[j][2];
    }
    N_[33] = t0; N_[34] = t1; N_[35] = t2;
    N_[36] = noised; N_[37] = keep; N_[38] = (float)seq[r]; N_[39] = 0.0f;
}

// ---------------- helpers ----------------
__device__ __forceinline__ float ex2(float x) {
    float y;
    asm("ex2.approx.f32 %0, %1;" : "=f"(y) : "f"(x));
    return y;
}

__device__ __forceinline__ float reduce_2pi(float ang) {
    const float INV_2PI = 0.15915494309189535f;
    const float HI = 6.28125f;
    const float LO = 1.9353071795864769e-3f;
    float k = rintf(ang * INV_2PI);
    float r = fmaf(-k, HI, ang);
    r = fmaf(-k, LO, r);
    return r;
}

// ---------------- edge kernel: TWO edges per warp (half-warp per edge) ----------------
__global__ void __launch_bounds__(256) edge_kernel(const int* __restrict__ ei,
                                                   float* __restrict__ out) {
    const unsigned FULL = 0xFFFFFFFFu;
    int W = (blockIdx.x * 256 + threadIdx.x) >> 5;   // warp id: edges 2W, 2W+1
    int lane = threadIdx.x & 31;
    int hl = lane & 15;        // lane within half
    int hb = lane & 16;        // half base (0 or 16)
    int half = lane >> 4;

    int2 dpair = *(const int2*)(ei + 2 * W);             // dst of edges 2W, 2W+1
    int2 spair = *(const int2*)(ei + N_EDGE + 2 * W);    // src

    int dst = half ? dpair.y : dpair.x;
    int src = half ? spair.y : spair.x;

    const float* SR = g_node + src * REC;
    const float* DR = g_node + dst * REC;

    // per-half cooperative loads (lanes 0..11 of each half)
    float sv = 0.0f, dv = 0.0f, lv = 0.0f, bv = 0.0f;
    if (hl < 12) {
        sv = SR[hl];          // src bb
        dv = DR[hl];          // dst bb
        lv = SR[12 + hl];     // src local * keep_s
        bv = SR[24 + hl];     // src R (9) + t (3)
    }
    // per-half scalar records (broadcast within half, 2 addresses per warp)
    float4 ssE = *(const float4*)(SR + 36);   // noised_s, keep_s, seqf_s
    float4 dsE = *(const float4*)(DR + 36);   // noised_d, keep_d, seqf_d

    float* rowE = out + (size_t)(2 * W + half) * FDIM;
    float* row0 = out + (size_t)(2 * W) * FDIM;
    float* row1 = row0 + FDIM;

    // ---- segment A: cols 0..43, single pass, both edges at once ----
    {
        float lf = (float)hl;
        // col hl: 0=noised_d, 1=noised_s, 2..15 = src one-hot idx hl-2
        float v0;
        if (hl == 0)      v0 = dsE.x;
        else if (hl == 1) v0 = ssE.x;
        else              v0 = (ssE.z == lf - 2.0f) ? ssE.y : 0.0f;
        __stcs(rowE + hl, v0);
        // col 16+hl: hl<7 -> src idx hl+14; else dst idx hl-7
        float v1 = (hl < 7) ? ((ssE.z == lf + 14.0f) ? ssE.y : 0.0f)
                            : ((dsE.z == lf - 7.0f)  ? dsE.y : 0.0f);
        __stcs(rowE + 16 + hl, v1);
        // col 32+hl (hl<12): dst idx hl+9
        if (hl < 12) __stcs(rowE + 32 + hl, (dsE.z == lf + 9.0f) ? dsE.y : 0.0f);
    }

    // ---- distances: every lane owns one pair of its half's edge ----
    float dve = 1e-8f - dv;
    int i3 = ((lane >> 2) & 3) * 3;
    int j3 = (lane & 3) * 3;
    float dx = __shfl_sync(FULL, sv, hb + i3 + 0) + __shfl_sync(FULL, dve, hb + j3 + 0);
    float dy = __shfl_sync(FULL, sv, hb + i3 + 1) + __shfl_sync(FULL, dve, hb + j3 + 1);
    float dz = __shfl_sync(FULL, sv, hb + i3 + 2) + __shfl_sync(FULL, dve, hb + j3 + 2);
    float dist = sqrtf(fmaf(dx, dx, fmaf(dy, dy, dz * dz)));
    // dist for edge e lives in lanes [e*16, e*16+16), pair p at lane e*16+p

    // ---- segment B: RBF, cols 44..299 as float4 slots (STG.128), per edge ----
    // exp(-((D-mu)/1.25)^2) == 2^(-((D-mu)*C)^2), C = 0.8*sqrt(log2 e)
    const float C = 0.9608979270291598f;
    int rbase = (lane * 4) & 15;
    float c0 = fmaf((float)(rbase + 0), 4.0f / 3.0f, 2.0f) * (-C);
    float c1 = fmaf((float)(rbase + 1), 4.0f / 3.0f, 2.0f) * (-C);
    float c2 = fmaf((float)(rbase + 2), 4.0f / 3.0f, 2.0f) * (-C);
    float c3 = fmaf((float)(rbase + 3), 4.0f / 3.0f, 2.0f) * (-C);
    int pbase = lane >> 2;
    #pragma unroll
    for (int e = 0; e < 2; ++e) {
        float4* rb4 = (float4*)((e ? row1 : row0) + 44);
        #pragma unroll
        for (int it = 0; it < 2; ++it) {
            float D = __shfl_sync(FULL, dist, e * 16 + pbase + it * 8);
            float z0 = fmaf(D, C, c0);
            float z1 = fmaf(D, C, c1);
            float z2 = fmaf(D, C, c2);
            float z3 = fmaf(D, C, c3);
            float4 v;
            v.x = ex2(-z0 * z0);
            v.y = ex2(-z1 * z1);
            v.z = ex2(-z2 * z2);
            v.w = ex2(-z3 * z3);
            __stcs(rb4 + it * 32 + lane, v);
        }
    }

    // ---- segment C: positional encoding, cols 300..315, per half ----
    {
        float dpos = (float)(dst - src);
        float ang = dpos * g_freq[hl & 7];
        float r = reduce_2pi(ang);
        float v = (hl < 8) ? __cosf(r) : __sinf(r);
        __stcs(rowE + 300 + hl, v);
    }

    // ---- segment D: cols 316..327 src_bb_local (premul), 328..339 dst_in_src ----
    {
        int k3 = (hl / 3) * 3, i_ = hl - k3;    // valid for hl<12; hl>=12 unused
        float r0 = __shfl_sync(FULL, bv, hb + 0 + i_);
        float r1 = __shfl_sync(FULL, bv, hb + 3 + i_);
        float r2 = __shfl_sync(FULL, bv, hb + 6 + i_);
        float t0 = __shfl_sync(FULL, bv, hb + 9);
        float t1 = __shfl_sync(FULL, bv, hb + 10);
        float t2 = __shfl_sync(FULL, bv, hb + 11);
        float b0 = __shfl_sync(FULL, dv, hb + k3 + 0);
        float b1 = __shfl_sync(FULL, dv, hb + k3 + 1);
        float b2 = __shfl_sync(FULL, dv, hb + k3 + 2);
        float dis = fmaf(r0, b0 - t0, fmaf(r1, b1 - t1, r2 * (b2 - t2)));
        if (hl < 12) {
            __stcs(rowE + 316 + hl, lv);             // already premultiplied by keep_s
            __stcs(rowE + 328 + hl, dis * dsE.y);    // * keep_d
        }
    }
}

// ---------------- launch ----------------
extern "C" void kernel_launch(void* const* d_in, const int* in_sizes, int n_in,
                              void* d_out, int out_size) {
    const float* atom14 = (const float*)d_in[0];
    const float* rig    = (const float*)d_in[1];
    const int*   seq    = (const int*)d_in[2];
    const void*  mask   = d_in[3];
    const int*   ei     = (const int*)d_in[4];
    float*       out    = (float*)d_out;

    node_kernel<<<(N_RES + 127) / 128, 128>>>(atom14, rig, seq, mask);
    edge_kernel<<<N_EDGE / 16, 256>>>(ei, out);   // 2 edges per warp, 8 warps per block
}

// round 17
// speedup vs baseline: 1.0384x; 1.0202x over previous
#include <cuda_runtime.h>
#include <math.h>

#define N_RES  20000
#define N_EDGE 640000
#define FDIM   340
#define REC    48

// ---------------- device scratch (no allocations allowed) ----------------
__device__ float g_freq[8];             // positional frequencies (match XLA f32 exp)
// packed per-residue record (48 floats = 192B):
// [0:12) bb (N,CA,C,CB) | [12:24) local=R^T(bb-t) premul by keep | [24:33) R[j*3+i] | [33:36) t
// [36] noised [37] keep [38] seq_f [39] pad
__device__ float g_node[N_RES * REC];

// ---------------- per-residue precompute (mask dtype detected inline) ----------------
__global__ void node_kernel(const float* __restrict__ atom14,
                            const float* __restrict__ rig,
                            const int*   __restrict__ seq,
                            const void*  __restrict__ maskp) {
    int r = blockIdx.x * blockDim.x + threadIdx.x;
    if (r >= N_RES) return;

    // positional freqs (threads 0..7): exact f32 rounding like XLA
    if (r < 8) {
        const float basef = -0.5756462732485115f;   // float(-ln(10000)/16)
        float arg = (float)(2 * r) * basef;
        g_freq[r] = (float)exp((double)arg);
    }

    // mask dtype detection: scan 64 words (uniform across threads -> L1 broadcast)
    const unsigned* mw = (const unsigned*)maskp;
    bool isF = false, isB = false;
    #pragma unroll
    for (int i = 0; i < 64; ++i) {
        unsigned v = __ldg(mw + i);
        isF |= (v == 0x3F800000u);
        isB |= (v != 0u && v != 1u);
    }
    int mode = isB ? 2 : (isF ? 0 : 1);

    unsigned char mv;
    if (mode == 2)      mv = (((const unsigned char*)maskp)[r] != 0);
    else if (mode == 1) mv = (((const int*)maskp)[r] != 0);
    else                mv = (((const float*)maskp)[r] != 0.0f);
    float noised = mv ? 1.0f : 0.0f;
    float keep   = 1.0f - noised;

    const float* a = atom14 + (size_t)r * 14 * 3;
    float n0 = a[0], n1 = a[1], n2 = a[2];
    float ca0 = a[3], ca1 = a[4], ca2 = a[5];
    float c0 = a[6], c1 = a[7], c2 = a[8];

    float bx = ca0 - n0, by = ca1 - n1, bz = ca2 - n2;
    float cx = c0 - ca0, cy = c1 - ca1, cz = c2 - ca2;
    float ax = by * cz - bz * cy;
    float ay = bz * cx - bx * cz;
    float az = bx * cy - by * cx;
    float cb0 = -0.58273431f * ax + 0.56802827f * bx - 0.54067466f * cx + ca0;
    float cb1 = -0.58273431f * ay + 0.56802827f * by - 0.54067466f * cy + ca1;
    float cb2 = -0.58273431f * az + 0.56802827f * bz - 0.54067466f * cz + ca2;

    float bb[4][3] = {{n0, n1, n2}, {ca0, ca1, ca2}, {c0, c1, c2}, {cb0, cb1, cb2}};

    const float* q = rig + (size_t)r * 7;
    float w = q[0], x = q[1], y = q[2], z = q[3];
    float inv = rsqrtf(w * w + x * x + y * y + z * z);
    w *= inv; x *= inv; y *= inv; z *= inv;

    float R[3][3];
    R[0][0] = 1.0f - 2.0f * (y * y + z * z);
    R[0][1] = 2.0f * (x * y - w * z);
    R[0][2] = 2.0f * (x * z + w * y);
    R[1][0] = 2.0f * (x * y + w * z);
    R[1][1] = 1.0f - 2.0f * (x * x + z * z);
    R[1][2] = 2.0f * (y * z - w * x);
    R[2][0] = 2.0f * (x * z - w * y);
    R[2][1] = 2.0f * (y * z + w * x);
    R[2][2] = 1.0f - 2.0f * (x * x + y * y);

    float t0 = q[4], t1 = q[5], t2 = q[6];

    // build the full 48-float record in registers, then store as 12 STG.128
    float rec[REC];
    #pragma unroll
    for (int k = 0; k < 4; ++k) {
        rec[k * 3 + 0] = bb[k][0];
        rec[k * 3 + 1] = bb[k][1];
        rec[k * 3 + 2] = bb[k][2];
        float d0 = bb[k][0] - t0, d1 = bb[k][1] - t1, d2 = bb[k][2] - t2;
        #pragma unroll
        for (int i = 0; i < 3; ++i) {
            rec[12 + k * 3 + i] = (R[0][i] * d0 + R[1][i] * d1 + R[2][i] * d2) * keep;
        }
    }
    #pragma unroll
    for (int j = 0; j < 3; ++j) {
        rec[24 + j * 3 + 0] = R[j][0];
        rec[24 + j * 3 + 1] = R[j][1];
        rec[24 + j * 3 + 2] = R[j][2];
    }
    rec[33] = t0; rec[34] = t1; rec[35] = t2;
    rec[36] = noised; rec[37] = keep; rec[38] = (float)seq[r]; rec[39] = 0.0f;
    #pragma unroll
    for (int i = 40; i < REC; ++i) rec[i] = 0.0f;

    float4* dst4 = (float4*)(g_node + r * REC);   // r*192B, 16B-aligned
    #pragma unroll
    for (int i = 0; i < REC / 4; ++i) {
        float4 v;
        v.x = rec[4 * i + 0];
        v.y = rec[4 * i + 1];
        v.z = rec[4 * i + 2];
        v.w = rec[4 * i + 3];
        dst4[i] = v;
    }
}

// ---------------- helpers ----------------
__device__ __forceinline__ float ex2(float x) {
    float y;
    asm("ex2.approx.f32 %0, %1;" : "=f"(y) : "f"(x));
    return y;
}

__device__ __forceinline__ float reduce_2pi(float ang) {
    const float INV_2PI = 0.15915494309189535f;
    const float HI = 6.28125f;
    const float LO = 1.9353071795864769e-3f;
    float k = rintf(ang * INV_2PI);
    float r = fmaf(-k, HI, ang);
    r = fmaf(-k, LO, r);
    return r;
}

// ---------------- edge kernel: TWO edges per warp (half-warp per edge) ----------------
// (R11/R16 winner, verbatim)
__global__ void __launch_bounds__(256) edge_kernel(const int* __restrict__ ei,
                                                   float* __restrict__ out) {
    const unsigned FULL = 0xFFFFFFFFu;
    int W = (blockIdx.x * 256 + threadIdx.x) >> 5;   // warp id: edges 2W, 2W+1
    int lane = threadIdx.x & 31;
    int hl = lane & 15;        // lane within half
    int hb = lane & 16;        // half base (0 or 16)
    int half = lane >> 4;

    int2 dpair = *(const int2*)(ei + 2 * W);             // dst of edges 2W, 2W+1
    int2 spair = *(const int2*)(ei + N_EDGE + 2 * W);    // src

    int dst = half ? dpair.y : dpair.x;
    int src = half ? spair.y : spair.x;

    const float* SR = g_node + src * REC;
    const float* DR = g_node + dst * REC;

    // per-half cooperative loads (lanes 0..11 of each half)
    float sv = 0.0f, dv = 0.0f, lv = 0.0f, bv = 0.0f;
    if (hl < 12) {
        sv = SR[hl];          // src bb
        dv = DR[hl];          // dst bb
        lv = SR[12 + hl];     // src local * keep_s
        bv = SR[24 + hl];     // src R (9) + t (3)
    }
    // per-half scalar records (broadcast within half, 2 addresses per warp)
    float4 ssE = *(const float4*)(SR + 36);   // noised_s, keep_s, seqf_s
    float4 dsE = *(const float4*)(DR + 36);   // noised_d, keep_d, seqf_d

    float* rowE = out + (size_t)(2 * W + half) * FDIM;
    float* row0 = out + (size_t)(2 * W) * FDIM;
    float* row1 = row0 + FDIM;

    // ---- segment A: cols 0..43, single pass, both edges at once ----
    {
        float lf = (float)hl;
        // col hl: 0=noised_d, 1=noised_s, 2..15 = src one-hot idx hl-2
        float v0;
        if (hl == 0)      v0 = dsE.x;
        else if (hl == 1) v0 = ssE.x;
        else              v0 = (ssE.z == lf - 2.0f) ? ssE.y : 0.0f;
        __stcs(rowE + hl, v0);
        // col 16+hl: hl<7 -> src idx hl+14; else dst idx hl-7
        float v1 = (hl < 7) ? ((ssE.z == lf + 14.0f) ? ssE.y : 0.0f)
                            : ((dsE.z == lf - 7.0f)  ? dsE.y : 0.0f);
        __stcs(rowE + 16 + hl, v1);
        // col 32+hl (hl<12): dst idx hl+9
        if (hl < 12) __stcs(rowE + 32 + hl, (dsE.z == lf + 9.0f) ? dsE.y : 0.0f);
    }

    // ---- distances: every lane owns one pair of its half's edge ----
    float dve = 1e-8f - dv;
    int i3 = ((lane >> 2) & 3) * 3;
    int j3 = (lane & 3) * 3;
    float dx = __shfl_sync(FULL, sv, hb + i3 + 0) + __shfl_sync(FULL, dve, hb + j3 + 0);
    float dy = __shfl_sync(FULL, sv, hb + i3 + 1) + __shfl_sync(FULL, dve, hb + j3 + 1);
    float dz = __shfl_sync(FULL, sv, hb + i3 + 2) + __shfl_sync(FULL, dve, hb + j3 + 2);
    float dist = sqrtf(fmaf(dx, dx, fmaf(dy, dy, dz * dz)));
    // dist for edge e lives in lanes [e*16, e*16+16), pair p at lane e*16+p

    // ---- segment B: RBF, cols 44..299 as float4 slots (STG.128), per edge ----
    // exp(-((D-mu)/1.25)^2) == 2^(-((D-mu)*C)^2), C = 0.8*sqrt(log2 e)
    const float C = 0.9608979270291598f;
    int rbase = (lane * 4) & 15;
    float c0 = fmaf((float)(rbase + 0), 4.0f / 3.0f, 2.0f) * (-C);
    float c1 = fmaf((float)(rbase + 1), 4.0f / 3.0f, 2.0f) * (-C);
    float c2 = fmaf((float)(rbase + 2), 4.0f / 3.0f, 2.0f) * (-C);
    float c3 = fmaf((float)(rbase + 3), 4.0f / 3.0f, 2.0f) * (-C);
    int pbase = lane >> 2;
    #pragma unroll
    for (int e = 0; e < 2; ++e) {
        float4* rb4 = (float4*)((e ? row1 : row0) + 44);
        #pragma unroll
        for (int it = 0; it < 2; ++it) {
            float D = __shfl_sync(FULL, dist, e * 16 + pbase + it * 8);
            float z0 = fmaf(D, C, c0);
            float z1 = fmaf(D, C, c1);
            float z2 = fmaf(D, C, c2);
            float z3 = fmaf(D, C, c3);
            float4 v;
            v.x = ex2(-z0 * z0);
            v.y = ex2(-z1 * z1);
            v.z = ex2(-z2 * z2);
            v.w = ex2(-z3 * z3);
            __stcs(rb4 + it * 32 + lane, v);
        }
    }

    // ---- segment C: positional encoding, cols 300..315, per half ----
    {
        float dpos = (float)(dst - src);
        float ang = dpos * g_freq[hl & 7];
        float r = reduce_2pi(ang);
        float v = (hl < 8) ? __cosf(r) : __sinf(r);
        __stcs(rowE + 300 + hl, v);
    }

    // ---- segment D: cols 316..327 src_bb_local (premul), 328..339 dst_in_src ----
    {
        int k3 = (hl / 3) * 3, i_ = hl - k3;    // valid for hl<12; hl>=12 unused
        float r0 = __shfl_sync(FULL, bv, hb + 0 + i_);
        float r1 = __shfl_sync(FULL, bv, hb + 3 + i_);
        float r2 = __shfl_sync(FULL, bv, hb + 6 + i_);
        float t0 = __shfl_sync(FULL, bv, hb + 9);
        float t1 = __shfl_sync(FULL, bv, hb + 10);
        float t2 = __shfl_sync(FULL, bv, hb + 11);
        float b0 = __shfl_sync(FULL, dv, hb + k3 + 0);
        float b1 = __shfl_sync(FULL, dv, hb + k3 + 1);
        float b2 = __shfl_sync(FULL, dv, hb + k3 + 2);
        float dis = fmaf(r0, b0 - t0, fmaf(r1, b1 - t1, r2 * (b2 - t2)));
        if (hl < 12) {
            __stcs(rowE + 316 + hl, lv);             // already premultiplied by keep_s
            __stcs(rowE + 328 + hl, dis * dsE.y);    // * keep_d
        }
    }
}

// ---------------- launch ----------------
extern "C" void kernel_launch(void* const* d_in, const int* in_sizes, int n_in,
                              void* d_out, int out_size) {
    const float* atom14 = (const float*)d_in[0];
    const float* rig    = (const float*)d_in[1];
    const int*   seq    = (const int*)d_in[2];
    const void*  mask   = d_in[3];
    const int*   ei     = (const int*)d_in[4];
    float*       out    = (float*)d_out;

    node_kernel<<<(N_RES + 127) / 128, 128>>>(atom14, rig, seq, mask);
    edge_kernel<<<N_EDGE / 16, 256>>>(ei, out);   // 2 edges per warp, 8 warps per block
}